// round 11
// baseline (speedup 1.0000x reference)
#include <cuda_runtime.h>
#include <cuda_fp16.h>
#include <cstdint>

#define NB  16
#define NC  512
#define NK  512
#define NHW 4096
#define NP  (NB * NHW)   // 65536 pixels

#define RESCUE_T 0.2f

// --------------------------------------------------------------------------
// Allocation-free scratch
// --------------------------------------------------------------------------
__device__ __half g_x16[(size_t)NP * NC];   // x fp16 hi, [p][c] K-major
__device__ __half g_xl[(size_t)NP * NC];    // x fp16 residual limb
__device__ __half g_c16[NK * NC];           // centers fp16 [k][c]
__device__ float  g_centT[NC * NK];         // centers fp32 transposed [c][k]
__device__ float  g_csq[NK];
__device__ unsigned long long g_partk[(size_t)NP * 4];
__device__ float              g_partv[(size_t)NP * 4];
__device__ int g_count;
__device__ int g_queue[NP];

// --------------------------------------------------------------------------
// Helpers
// --------------------------------------------------------------------------
__device__ __forceinline__ uint32_t smem_u32(const void* p) {
    uint32_t a;
    asm("{ .reg .u64 t; cvta.to.shared.u64 t, %1; cvt.u32.u64 %0, t; }"
        : "=r"(a) : "l"(p));
    return a;
}
__device__ __forceinline__ unsigned long long enc_key(float v, int k) {
    unsigned u = __float_as_uint(v);
    u = (u & 0x80000000u) ? ~u : (u | 0x80000000u);
    return ((unsigned long long)u << 32) | (unsigned)k;
}
__device__ __forceinline__ float key_val(unsigned long long key) {
    unsigned u = (unsigned)(key >> 32);
    unsigned b = (u & 0x80000000u) ? (u & 0x7FFFFFFFu) : ~u;
    return __uint_as_float(b);
}
__device__ __forceinline__ void t2merge(unsigned long long& k1, float& v2,
                                        unsigned long long ok1, float ov2) {
    if (ok1 < k1) { v2 = fminf(key_val(k1), ov2); k1 = ok1; }
    else          { v2 = fminf(v2, key_val(ok1)); }
}
__device__ __forceinline__ void ldmx4(uint32_t* r, uint32_t addr) {
    asm volatile("ldmatrix.sync.aligned.m8n8.x4.shared.b16 {%0,%1,%2,%3}, [%4];"
                 : "=r"(r[0]), "=r"(r[1]), "=r"(r[2]), "=r"(r[3]) : "r"(addr));
}
// non-volatile: pure register op — lets the scheduler interleave with loads
__device__ __forceinline__ void mma16816(float* d, const uint32_t* a,
                                         uint32_t b0, uint32_t b1) {
    asm("mma.sync.aligned.m16n8k16.row.col.f32.f16.f16.f32 "
        "{%0,%1,%2,%3}, {%4,%5,%6,%7}, {%8,%9}, {%0,%1,%2,%3};"
        : "+f"(d[0]), "+f"(d[1]), "+f"(d[2]), "+f"(d[3])
        : "r"(a[0]), "r"(a[1]), "r"(a[2]), "r"(a[3]), "r"(b0), "r"(b1));
}

// --------------------------------------------------------------------------
// Prep: one block per code k — fp16 convert + fp32 transpose + fp64 csq
// --------------------------------------------------------------------------
__global__ void conv_cent(const float* __restrict__ cent) {
    __shared__ double red[128];
    const int k = blockIdx.x;
    const int t = threadIdx.x;
    if (k == 0 && t == 0) g_count = 0;

    float f0 = cent[k * NC + t];
    float f1 = cent[k * NC + t + 256];
    g_c16[k * NC + t]        = __float2half_rn(f0);
    g_c16[k * NC + t + 256]  = __float2half_rn(f1);
    g_centT[t * NK + k]          = f0;
    g_centT[(t + 256) * NK + k]  = f1;

    double s = (double)f0 * f0 + (double)f1 * f1;
    // warp reduce then smem reduce (256 threads -> 8 partials)
    #pragma unroll
    for (int d = 16; d > 0; d >>= 1)
        s += __shfl_xor_sync(0xFFFFFFFFu, s, d);
    if ((t & 31) == 0) red[t >> 5] = s;
    __syncthreads();
    if (t == 0) {
        double tot = 0.0;
        #pragma unroll
        for (int w = 0; w < 8; ++w) tot += red[w];
        g_csq[k] = (float)tot;
    }
}

// x (B,C,H,W) fp32 -> [p][c] fp16 hi + residual limb via smem transpose
__global__ void convert_x(const float* __restrict__ x) {
    __shared__ float s[64][65];
    const int p0 = blockIdx.x * 64;
    const int c0 = blockIdx.y * 64;
    const int b   = p0 >> 12;
    const int hw0 = p0 & 4095;
    const int t = threadIdx.x;
    const float* src = x + (size_t)b * NC * NHW + hw0;

    #pragma unroll
    for (int i = 0; i < 4; ++i) {
        int cl = i * 16 + (t >> 4);
        int pl = (t & 15) * 4;
        float4 v = *reinterpret_cast<const float4*>(src + (size_t)(c0 + cl) * NHW + pl);
        s[cl][pl] = v.x; s[cl][pl + 1] = v.y; s[cl][pl + 2] = v.z; s[cl][pl + 3] = v.w;
    }
    __syncthreads();

    {
        const int pl  = t >> 2;            // pixel 0..63
        const int c16 = (t & 3) << 4;      // 16 channels
        unsigned uh[8], ul[8];
        #pragma unroll
        for (int j = 0; j < 8; ++j) {
            float f0 = s[c16 + j * 2][pl];
            float f1 = s[c16 + j * 2 + 1][pl];
            __half h0 = __float2half_rn(f0), h1 = __float2half_rn(f1);
            __half l0 = __float2half_rn(f0 - __half2float(h0));
            __half l1 = __float2half_rn(f1 - __half2float(h1));
            __half2 hh = __halves2half2(h0, h1);
            __half2 ll = __halves2half2(l0, l1);
            uh[j] = *reinterpret_cast<unsigned*>(&hh);
            ul[j] = *reinterpret_cast<unsigned*>(&ll);
        }
        size_t off = (size_t)(p0 + pl) * NC + c0 + c16;
        *reinterpret_cast<uint4*>(&g_x16[off])     = make_uint4(uh[0], uh[1], uh[2], uh[3]);
        *reinterpret_cast<uint4*>(&g_x16[off + 8]) = make_uint4(uh[4], uh[5], uh[6], uh[7]);
        *reinterpret_cast<uint4*>(&g_xl[off])      = make_uint4(ul[0], ul[1], ul[2], ul[3]);
        *reinterpret_cast<uint4*>(&g_xl[off + 8])  = make_uint4(ul[4], ul[5], ul[6], ul[7]);
    }
}

// --------------------------------------------------------------------------
// Smem: 3 stages x 32 KB (A 16 KB + B 16 KB), 128 B rows, XOR swizzle on
// 16 B units (j ^= row&7). Top-2 scratch overlays stage 0 after mainloop.
// --------------------------------------------------------------------------
#define STG_BYTES 32768
#define B_OFF     16384
#define SMEM_TOTAL 98304

// --------------------------------------------------------------------------
// Main GEMM: CTA = 128 px x 128 codes (grid 2048 = 512 groups x 4 chunks).
// 8 stages of 64 channels, 3-stage cp.async ring, 1 barrier per stage,
// 4 k-steps (64 MMAs/warp) per barrier window.
// --------------------------------------------------------------------------
__global__ __launch_bounds__(256, 2)
void hmma_top2() {
    extern __shared__ __align__(1024) char smem[];
    const uint32_t sb = smem_u32(smem);
    const int tid  = threadIdx.x;
    const int lane = tid & 31;
    const int wid  = tid >> 5;
    const int wm   = wid >> 2;
    const int wn   = wid & 3;

    const int grp = blockIdx.x >> 2;
    const int kc  = blockIdx.x & 3;
    const int p0  = grp * 128;

    // ---- loader state: 8 chunks of 16 B per thread per stage ----
    const char* srcp[8];
    uint32_t dsto[8];
    #pragma unroll
    for (int u = 0; u < 8; ++u) {
        int q   = tid + (u << 8);           // 0..2047
        int ab  = q >> 10;                  // 0=A(x), 1=B(centers)
        int row = (q >> 3) & 127;
        int j   = q & 7;
        srcp[u] = ab
            ? (const char*)(g_c16 + (size_t)(kc * 128 + row) * NC + j * 8)
            : (const char*)(g_x16 + (size_t)(p0 + row) * NC + j * 8);
        dsto[u] = sb + ab * B_OFF + row * 128 + ((j ^ (row & 7)) << 4);
    }

    // ---- ldmatrix row bases (swizzle bits constant under row+16 steps) ----
    const int rA  = wm * 64 + (lane & 15);
    const int swA = rA & 7;
    const int rB  = wn * 32 + (lane & 15);
    const int swB = rB & 7;
    const int khalf = lane >> 4;

    float acc[4][4][4];
    #pragma unroll
    for (int m = 0; m < 4; ++m)
        #pragma unroll
        for (int n = 0; n < 4; ++n)
            #pragma unroll
            for (int r = 0; r < 4; ++r) acc[m][n][r] = 0.0f;

    // ---- prologue: stages 0,1 ----
    #pragma unroll
    for (int i = 0; i < 2; ++i) {
        #pragma unroll
        for (int u = 0; u < 8; ++u)
            asm volatile("cp.async.cg.shared.global [%0], [%1], 16;"
                :: "r"(dsto[u] + i * STG_BYTES), "l"(srcp[u] + i * 128)
                : "memory");
        asm volatile("cp.async.commit_group;" ::: "memory");
    }

    #pragma unroll
    for (int i = 0; i < 8; ++i) {
        if (i < 6)      asm volatile("cp.async.wait_group 1;" ::: "memory");
        else            asm volatile("cp.async.wait_group 0;" ::: "memory");
        __syncthreads();
        if (i + 2 < 8) {
            #pragma unroll
            for (int u = 0; u < 8; ++u)
                asm volatile("cp.async.cg.shared.global [%0], [%1], 16;"
                    :: "r"(dsto[u] + ((i + 2) % 3) * STG_BYTES),
                       "l"(srcp[u] + (i + 2) * 128)
                    : "memory");
            asm volatile("cp.async.commit_group;" ::: "memory");
        }
        const uint32_t S = (i % 3) * STG_BYTES;
        #pragma unroll
        for (int ks = 0; ks < 4; ++ks) {
            const int jj = ks * 2 + khalf;
            uint32_t ah[4][4];
            #pragma unroll
            for (int mt = 0; mt < 4; ++mt)
                ldmx4(ah[mt], sb + S + (rA + mt * 16) * 128 + ((jj ^ swA) << 4));
            #pragma unroll
            for (int nt = 0; nt < 2; ++nt) {
                uint32_t bf[4];
                ldmx4(bf, sb + S + B_OFF + (rB + nt * 16) * 128 + ((jj ^ swB) << 4));
                #pragma unroll
                for (int sub = 0; sub < 2; ++sub) {
                    const int nn = nt * 2 + sub;
                    #pragma unroll
                    for (int mt = 0; mt < 4; ++mt)
                        mma16816(acc[mt][nn], ah[mt], bf[sub], bf[sub + 2]);
                }
            }
        }
    }
    __syncthreads();   // before top-2 scratch overlays stage 0

    // ---- epilogue: per-row top-2 in registers, merge via shfl + smem ----
    unsigned long long* smk = (unsigned long long*)smem;            // 4 KB
    float*              smv = (float*)(smem + 4096);                // 2 KB
    const int r4 = lane >> 2, c2 = (lane & 3) << 1;

    #pragma unroll
    for (int mt = 0; mt < 4; ++mt) {
        unsigned long long k1a = ~0ULL, k1b = ~0ULL;
        float v2a = 3.0e38f, v2b = 3.0e38f;
        const int row0 = wm * 64 + mt * 16 + r4;
        #pragma unroll
        for (int nn = 0; nn < 4; ++nn) {
            #pragma unroll
            for (int cc = 0; cc < 2; ++cc) {
                const int col = wn * 32 + nn * 8 + c2 + cc;
                const int kg  = kc * 128 + col;
                const float cq = g_csq[kg];
                float va = fmaf(-2.0f, acc[mt][nn][cc], cq);
                float vb = fmaf(-2.0f, acc[mt][nn][cc + 2], cq);
                unsigned long long ea = enc_key(va, kg);
                unsigned long long eb = enc_key(vb, kg);
                if (ea < k1a) { v2a = fminf(v2a, key_val(k1a)); k1a = ea; }
                else           v2a = fminf(v2a, va);
                if (eb < k1b) { v2b = fminf(v2b, key_val(k1b)); k1b = eb; }
                else           v2b = fminf(v2b, vb);
            }
        }
        #pragma unroll
        for (int d = 1; d <= 2; d <<= 1) {
            unsigned long long oka = __shfl_xor_sync(0xFFFFFFFFu, k1a, d);
            float ova              = __shfl_xor_sync(0xFFFFFFFFu, v2a, d);
            t2merge(k1a, v2a, oka, ova);
            unsigned long long okb = __shfl_xor_sync(0xFFFFFFFFu, k1b, d);
            float ovb              = __shfl_xor_sync(0xFFFFFFFFu, v2b, d);
            t2merge(k1b, v2b, okb, ovb);
        }
        if ((lane & 3) == 0) {
            smk[row0 * 4 + wn] = k1a;  smv[row0 * 4 + wn] = v2a;
            smk[(row0 + 8) * 4 + wn] = k1b;  smv[(row0 + 8) * 4 + wn] = v2b;
        }
    }
    __syncthreads();

    if (tid < 128) {
        unsigned long long k1 = smk[tid * 4];
        float v2 = smv[tid * 4];
        #pragma unroll
        for (int w = 1; w < 4; ++w) t2merge(k1, v2, smk[tid * 4 + w], smv[tid * 4 + w]);
        g_partk[(size_t)(p0 + tid) * 4 + kc] = k1;
        g_partv[(size_t)(p0 + tid) * 4 + kc] = v2;
    }
}

// --------------------------------------------------------------------------
// Finalize: global top-2 across chunks; enqueue tight margins for rescue.
// --------------------------------------------------------------------------
__global__ void finalize(float* __restrict__ out) {
    int p = blockIdx.x * 256 + threadIdx.x;
    unsigned long long k1 = g_partk[(size_t)p * 4];
    float v2 = g_partv[(size_t)p * 4];
    #pragma unroll
    for (int c = 1; c < 4; ++c)
        t2merge(k1, v2, g_partk[(size_t)p * 4 + c], g_partv[(size_t)p * 4 + c]);
    out[p] = (float)(int)(unsigned)(k1 & 0xFFFFFFFFULL);
    if (v2 - key_val(k1) < RESCUE_T) {
        int s = atomicAdd(&g_count, 1);
        g_queue[s] = p;
    }
}

// --------------------------------------------------------------------------
// Rescue: exact re-evaluation (x reconstructed from the two fp16 limbs —
// coalesced loads; abs error ~1e-7, far below any decidable margin).
// --------------------------------------------------------------------------
__global__ __launch_bounds__(256, 2)
void rescue(float* __restrict__ out) {
    __shared__ float xs[16][512];
    __shared__ unsigned long long best[16];
    const int t = threadIdx.x;
    const int cnt = g_count;

    for (int base = blockIdx.x * 16; base < cnt; base += 256 * 16) {
        const int nv = min(16, cnt - base);
        if (t < 16) best[t] = ~0ULL;
        for (int i = 0; i < nv; ++i) {
            int p = g_queue[base + i];
            const __half* sh = &g_x16[(size_t)p * NC];
            const __half* sl = &g_xl[(size_t)p * NC];
            xs[i][t]       = __half2float(sh[t])       + __half2float(sl[t]);
            xs[i][t + 256] = __half2float(sh[t + 256]) + __half2float(sl[t + 256]);
        }
        __syncthreads();

        float a0[16], a1[16];
        #pragma unroll
        for (int i = 0; i < 16; ++i) { a0[i] = 0.0f; a1[i] = 0.0f; }
        const float cq0 = g_csq[t], cq1 = g_csq[t + 256];

        #pragma unroll 4
        for (int cc = 0; cc < 512; ++cc) {
            float c0v = g_centT[cc * NK + t];
            float c1v = g_centT[cc * NK + t + 256];
            #pragma unroll
            for (int i = 0; i < 16; ++i) {
                float xv = xs[i][cc];
                a0[i] = fmaf(xv, c0v, a0[i]);
                a1[i] = fmaf(xv, c1v, a1[i]);
            }
        }
        #pragma unroll
        for (int i = 0; i < 16; ++i) {
            if (i < nv) {
                unsigned long long e0 = enc_key(fmaf(-2.0f, a0[i], cq0), t);
                unsigned long long e1 = enc_key(fmaf(-2.0f, a1[i], cq1), t + 256);
                atomicMin(&best[i], e0 < e1 ? e0 : e1);
            }
        }
        __syncthreads();
        if (t < nv)
            out[g_queue[base + t]] =
                (float)(int)(unsigned)(best[t] & 0xFFFFFFFFULL);
        __syncthreads();
    }
}

// --------------------------------------------------------------------------
// Launch
// --------------------------------------------------------------------------
extern "C" void kernel_launch(void* const* d_in, const int* in_sizes, int n_in,
                              void* d_out, int out_size) {
    const float* x    = (const float*)d_in[0];
    const float* cent = (const float*)d_in[1];
    if (n_in >= 2 && in_sizes[0] < in_sizes[1]) {
        const float* t = x; x = cent; cent = t;
    }

    cudaFuncSetAttribute(hmma_top2,
                         cudaFuncAttributeMaxDynamicSharedMemorySize, SMEM_TOTAL);

    conv_cent<<<NK, 256>>>(cent);
    dim3 tg(NP / 64, NC / 64);
    convert_x<<<tg, 256>>>(x);
    hmma_top2<<<NP / 128 * 4, 256, SMEM_TOTAL>>>();
    finalize<<<NP / 256, 256>>>((float*)d_out);
    rescue<<<256, 256>>>((float*)d_out);
    (void)out_size;
}

// round 12
// speedup vs baseline: 1.5242x; 1.5242x over previous
#include <cuda_runtime.h>
#include <cuda_fp16.h>
#include <cstdint>

#define NB  16
#define NC  512
#define NK  512
#define NHW 4096
#define NP  (NB * NHW)   // 65536 pixels

#define RESCUE_T 0.2f

// --------------------------------------------------------------------------
// Allocation-free scratch
// --------------------------------------------------------------------------
__device__ __half g_x16[(size_t)NP * NC];   // x fp16, [p][c] K-major
__device__ __half g_c16[NK * NC];           // centers fp16 [k][c]
__device__ float  g_centT[NC * NK];         // centers fp32 transposed [c][k]
__device__ float  g_csq[NK];
__device__ unsigned long long g_partk[(size_t)NP * 4];
__device__ float              g_partv[(size_t)NP * 4];
__device__ int g_count;
__device__ int g_queue[NP];

// --------------------------------------------------------------------------
// Helpers
// --------------------------------------------------------------------------
__device__ __forceinline__ uint32_t smem_u32(const void* p) {
    uint32_t a;
    asm("{ .reg .u64 t; cvta.to.shared.u64 t, %1; cvt.u32.u64 %0, t; }"
        : "=r"(a) : "l"(p));
    return a;
}
__device__ __forceinline__ unsigned long long enc_key(float v, int k) {
    unsigned u = __float_as_uint(v);
    u = (u & 0x80000000u) ? ~u : (u | 0x80000000u);
    return ((unsigned long long)u << 32) | (unsigned)k;
}
__device__ __forceinline__ float key_val(unsigned long long key) {
    unsigned u = (unsigned)(key >> 32);
    unsigned b = (u & 0x80000000u) ? (u & 0x7FFFFFFFu) : ~u;
    return __uint_as_float(b);
}
__device__ __forceinline__ void t2merge(unsigned long long& k1, float& v2,
                                        unsigned long long ok1, float ov2) {
    if (ok1 < k1) { v2 = fminf(key_val(k1), ov2); k1 = ok1; }
    else          { v2 = fminf(v2, key_val(ok1)); }
}
__device__ __forceinline__ void ldmx4(uint32_t* r, uint32_t addr) {
    asm volatile("ldmatrix.sync.aligned.m8n8.x4.shared.b16 {%0,%1,%2,%3}, [%4];"
                 : "=r"(r[0]), "=r"(r[1]), "=r"(r[2]), "=r"(r[3]) : "r"(addr));
}
__device__ __forceinline__ void mma16816(float* d, const uint32_t* a,
                                         uint32_t b0, uint32_t b1) {
    asm volatile(
        "mma.sync.aligned.m16n8k16.row.col.f32.f16.f16.f32 "
        "{%0,%1,%2,%3}, {%4,%5,%6,%7}, {%8,%9}, {%0,%1,%2,%3};"
        : "+f"(d[0]), "+f"(d[1]), "+f"(d[2]), "+f"(d[3])
        : "r"(a[0]), "r"(a[1]), "r"(a[2]), "r"(a[3]), "r"(b0), "r"(b1));
}

// --------------------------------------------------------------------------
// Prep: one block per code k — fp16 convert + fp32 transpose + fp64 csq
// --------------------------------------------------------------------------
__global__ void conv_cent(const float* __restrict__ cent) {
    __shared__ double red[8];
    const int k = blockIdx.x;
    const int t = threadIdx.x;
    if (k == 0 && t == 0) g_count = 0;

    float f0 = cent[k * NC + t];
    float f1 = cent[k * NC + t + 256];
    g_c16[k * NC + t]        = __float2half_rn(f0);
    g_c16[k * NC + t + 256]  = __float2half_rn(f1);
    g_centT[t * NK + k]          = f0;
    g_centT[(t + 256) * NK + k]  = f1;

    double s = (double)f0 * f0 + (double)f1 * f1;
    #pragma unroll
    for (int d = 16; d > 0; d >>= 1)
        s += __shfl_xor_sync(0xFFFFFFFFu, s, d);
    if ((t & 31) == 0) red[t >> 5] = s;
    __syncthreads();
    if (t == 0) {
        double tot = 0.0;
        #pragma unroll
        for (int w = 0; w < 8; ++w) tot += red[w];
        g_csq[k] = (float)tot;
    }
}

// x (B,C,H,W) fp32 -> [p][c] fp16 via smem transpose; coalesced writes
__global__ void convert_x(const float* __restrict__ x) {
    __shared__ float s[64][65];
    const int p0 = blockIdx.x * 64;
    const int c0 = blockIdx.y * 64;
    const int b   = p0 >> 12;
    const int hw0 = p0 & 4095;
    const int t = threadIdx.x;
    const float* src = x + (size_t)b * NC * NHW + hw0;

    #pragma unroll
    for (int i = 0; i < 4; ++i) {
        int cl = i * 16 + (t >> 4);
        int pl = (t & 15) * 4;
        float4 v = *reinterpret_cast<const float4*>(src + (size_t)(c0 + cl) * NHW + pl);
        s[cl][pl] = v.x; s[cl][pl + 1] = v.y; s[cl][pl + 2] = v.z; s[cl][pl + 3] = v.w;
    }
    __syncthreads();

    {
        const int pl  = t >> 2;
        const int c16 = (t & 3) << 4;
        unsigned u[8];
        #pragma unroll
        for (int j = 0; j < 8; ++j) {
            __half2 h = __halves2half2(__float2half_rn(s[c16 + j * 2][pl]),
                                       __float2half_rn(s[c16 + j * 2 + 1][pl]));
            u[j] = *reinterpret_cast<unsigned*>(&h);
        }
        __half* dst = &g_x16[(size_t)(p0 + pl) * NC + c0 + c16];
        *reinterpret_cast<uint4*>(dst)     = make_uint4(u[0], u[1], u[2], u[3]);
        *reinterpret_cast<uint4*>(dst + 8) = make_uint4(u[4], u[5], u[6], u[7]);
    }
}

// --------------------------------------------------------------------------
// Smem: 4 stages x 16 KB (A 8 KB + B 8 KB), 64 B rows, XOR swizzle.
// Then csq (512 B) + top2 key (4 KB) + v2 (2 KB).
// --------------------------------------------------------------------------
#define STG_BYTES 16384
#define B_OFF     8192
#define OFF_CSQ   65536
#define OFF_K2    66048
#define OFF_V2    70144
#define SMEM_TOTAL 72192

// --------------------------------------------------------------------------
// Main GEMM — identical to R10 (known 110.5 us).
// --------------------------------------------------------------------------
__global__ __launch_bounds__(256, 2)
void hmma_top2() {
    extern __shared__ __align__(1024) char smem[];
    const uint32_t sb = smem_u32(smem);
    const int tid  = threadIdx.x;
    const int lane = tid & 31;
    const int wid  = tid >> 5;
    const int wm   = wid >> 2;
    const int wn   = wid & 3;

    const int grp = blockIdx.x >> 2;
    const int kc  = blockIdx.x & 3;
    const int p0  = grp * 128;

    float* cs = (float*)(smem + OFF_CSQ);
    if (tid < 128) cs[tid] = g_csq[kc * 128 + tid];

    const char* srcp[4];
    uint32_t dsto[4];
    #pragma unroll
    for (int u = 0; u < 4; ++u) {
        int q   = tid + (u << 8);
        int ab  = q >> 9;
        int row = (q >> 2) & 127;
        int j   = q & 3;
        srcp[u] = ab
            ? (const char*)(g_c16 + (size_t)(kc * 128 + row) * NC + j * 8)
            : (const char*)(g_x16 + (size_t)(p0 + row) * NC + j * 8);
        dsto[u] = sb + ab * B_OFF + row * 64 + ((j ^ ((row >> 1) & 3)) << 4);
    }

    const int rA  = wm * 64 + (lane & 15);
    const int swA = (rA >> 1) & 3;
    const int rB  = wn * 32 + (lane & 15);
    const int swB = (rB >> 1) & 3;
    const int khalf = lane >> 4;
    uint32_t aadr[2][4], badr[2][2];
    #pragma unroll
    for (int ks = 0; ks < 2; ++ks) {
        const int jj = ks * 2 + khalf;
        #pragma unroll
        for (int mt = 0; mt < 4; ++mt)
            aadr[ks][mt] = sb + (rA + mt * 16) * 64 + ((jj ^ swA) << 4);
        #pragma unroll
        for (int nt = 0; nt < 2; ++nt)
            badr[ks][nt] = sb + B_OFF + (rB + nt * 16) * 64 + ((jj ^ swB) << 4);
    }

    float acc[4][4][4];
    #pragma unroll
    for (int m = 0; m < 4; ++m)
        #pragma unroll
        for (int n = 0; n < 4; ++n)
            #pragma unroll
            for (int r = 0; r < 4; ++r) acc[m][n][r] = 0.0f;

    #pragma unroll
    for (int i = 0; i < 3; ++i) {
        #pragma unroll
        for (int u = 0; u < 4; ++u)
            asm volatile("cp.async.cg.shared.global [%0], [%1], 16;"
                :: "r"(dsto[u] + (i & 3) * STG_BYTES), "l"(srcp[u] + i * 64)
                : "memory");
        asm volatile("cp.async.commit_group;" ::: "memory");
    }

    #pragma unroll
    for (int i = 0; i < 16; ++i) {
        if (i < 14)       asm volatile("cp.async.wait_group 2;" ::: "memory");
        else if (i == 14) asm volatile("cp.async.wait_group 1;" ::: "memory");
        else              asm volatile("cp.async.wait_group 0;" ::: "memory");
        __syncthreads();
        if (i + 3 < 16) {
            #pragma unroll
            for (int u = 0; u < 4; ++u)
                asm volatile("cp.async.cg.shared.global [%0], [%1], 16;"
                    :: "r"(dsto[u] + ((i + 3) & 3) * STG_BYTES),
                       "l"(srcp[u] + (i + 3) * 64)
                    : "memory");
            asm volatile("cp.async.commit_group;" ::: "memory");
        }
        const uint32_t S = (i & 3) * STG_BYTES;
        #pragma unroll
        for (int ks = 0; ks < 2; ++ks) {
            uint32_t ah[4][4];
            #pragma unroll
            for (int mt = 0; mt < 4; ++mt)
                ldmx4(ah[mt], aadr[ks][mt] + S);
            #pragma unroll
            for (int nt = 0; nt < 2; ++nt) {
                uint32_t bf[4];
                ldmx4(bf, badr[ks][nt] + S);
                #pragma unroll
                for (int sub = 0; sub < 2; ++sub) {
                    const int nn = nt * 2 + sub;
                    #pragma unroll
                    for (int mt = 0; mt < 4; ++mt)
                        mma16816(acc[mt][nn], ah[mt], bf[sub], bf[sub + 2]);
                }
            }
        }
    }

    unsigned long long* smk = (unsigned long long*)(smem + OFF_K2);
    float*              smv = (float*)(smem + OFF_V2);
    const int r4 = lane >> 2, c2 = (lane & 3) << 1;

    #pragma unroll
    for (int mt = 0; mt < 4; ++mt) {
        unsigned long long k1a = ~0ULL, k1b = ~0ULL;
        float v2a = 3.0e38f, v2b = 3.0e38f;
        const int row0 = wm * 64 + mt * 16 + r4;
        #pragma unroll
        for (int nn = 0; nn < 4; ++nn) {
            #pragma unroll
            for (int cc = 0; cc < 2; ++cc) {
                const int col = wn * 32 + nn * 8 + c2 + cc;
                const int kg  = kc * 128 + col;
                float va = fmaf(-2.0f, acc[mt][nn][cc], cs[col]);
                float vb = fmaf(-2.0f, acc[mt][nn][cc + 2], cs[col]);
                unsigned long long ea = enc_key(va, kg);
                unsigned long long eb = enc_key(vb, kg);
                if (ea < k1a) { v2a = fminf(v2a, key_val(k1a)); k1a = ea; }
                else           v2a = fminf(v2a, va);
                if (eb < k1b) { v2b = fminf(v2b, key_val(k1b)); k1b = eb; }
                else           v2b = fminf(v2b, vb);
            }
        }
        #pragma unroll
        for (int d = 1; d <= 2; d <<= 1) {
            unsigned long long oka = __shfl_xor_sync(0xFFFFFFFFu, k1a, d);
            float ova              = __shfl_xor_sync(0xFFFFFFFFu, v2a, d);
            t2merge(k1a, v2a, oka, ova);
            unsigned long long okb = __shfl_xor_sync(0xFFFFFFFFu, k1b, d);
            float ovb              = __shfl_xor_sync(0xFFFFFFFFu, v2b, d);
            t2merge(k1b, v2b, okb, ovb);
        }
        if ((lane & 3) == 0) {
            smk[row0 * 4 + wn] = k1a;  smv[row0 * 4 + wn] = v2a;
            smk[(row0 + 8) * 4 + wn] = k1b;  smv[(row0 + 8) * 4 + wn] = v2b;
        }
    }
    __syncthreads();

    if (tid < 128) {
        unsigned long long k1 = smk[tid * 4];
        float v2 = smv[tid * 4];
        #pragma unroll
        for (int w = 1; w < 4; ++w) t2merge(k1, v2, smk[tid * 4 + w], smv[tid * 4 + w]);
        g_partk[(size_t)(p0 + tid) * 4 + kc] = k1;
        g_partv[(size_t)(p0 + tid) * 4 + kc] = v2;
    }
}

// --------------------------------------------------------------------------
// Finalize: global top-2 across chunks; enqueue tight margins for rescue.
// --------------------------------------------------------------------------
__global__ void finalize(float* __restrict__ out) {
    int p = blockIdx.x * 256 + threadIdx.x;
    unsigned long long k1 = g_partk[(size_t)p * 4];
    float v2 = g_partv[(size_t)p * 4];
    #pragma unroll
    for (int c = 1; c < 4; ++c)
        t2merge(k1, v2, g_partk[(size_t)p * 4 + c], g_partv[(size_t)p * 4 + c]);
    out[p] = (float)(int)(unsigned)(k1 & 0xFFFFFFFFULL);
    if (v2 - key_val(k1) < RESCUE_T) {
        int s = atomicAdd(&g_count, 1);
        g_queue[s] = p;
    }
}

// --------------------------------------------------------------------------
// Rescue: exact fp32 re-evaluation; 8 px/block batches, fully-unrolled
// gather (32 loads in flight per thread).
// --------------------------------------------------------------------------
__global__ __launch_bounds__(256, 2)
void rescue(const float* __restrict__ x, float* __restrict__ out) {
    __shared__ float xs[8][512];
    __shared__ unsigned long long best[8];
    const int t = threadIdx.x;
    const int cnt = g_count;

    for (int base = blockIdx.x * 8; base < cnt; base += 512 * 8) {
        const int nv = min(8, cnt - base);
        if (t < 8) best[t] = ~0ULL;
        #pragma unroll
        for (int i = 0; i < 8; ++i) {
            if (i < nv) {
                int p = g_queue[base + i];
                int b = p >> 12, hw = p & 4095;
                const float* src = x + (size_t)b * NC * NHW + hw;
                xs[i][t]       = src[(size_t)t * NHW];
                xs[i][t + 256] = src[(size_t)(t + 256) * NHW];
            }
        }
        __syncthreads();

        float a0[8], a1[8];
        #pragma unroll
        for (int i = 0; i < 8; ++i) { a0[i] = 0.0f; a1[i] = 0.0f; }
        const float cq0 = g_csq[t], cq1 = g_csq[t + 256];

        #pragma unroll 4
        for (int cc = 0; cc < 512; ++cc) {
            float c0v = g_centT[cc * NK + t];
            float c1v = g_centT[cc * NK + t + 256];
            #pragma unroll
            for (int i = 0; i < 8; ++i) {
                float xv = xs[i][cc];
                a0[i] = fmaf(xv, c0v, a0[i]);
                a1[i] = fmaf(xv, c1v, a1[i]);
            }
        }
        #pragma unroll
        for (int i = 0; i < 8; ++i) {
            if (i < nv) {
                unsigned long long e0 = enc_key(fmaf(-2.0f, a0[i], cq0), t);
                unsigned long long e1 = enc_key(fmaf(-2.0f, a1[i], cq1), t + 256);
                atomicMin(&best[i], e0 < e1 ? e0 : e1);
            }
        }
        __syncthreads();
        if (t < nv)
            out[g_queue[base + t]] =
                (float)(int)(unsigned)(best[t] & 0xFFFFFFFFULL);
        __syncthreads();
    }
}

// --------------------------------------------------------------------------
// Launch
// --------------------------------------------------------------------------
extern "C" void kernel_launch(void* const* d_in, const int* in_sizes, int n_in,
                              void* d_out, int out_size) {
    const float* x    = (const float*)d_in[0];
    const float* cent = (const float*)d_in[1];
    if (n_in >= 2 && in_sizes[0] < in_sizes[1]) {
        const float* t = x; x = cent; cent = t;
    }

    cudaFuncSetAttribute(hmma_top2,
                         cudaFuncAttributeMaxDynamicSharedMemorySize, SMEM_TOTAL);

    conv_cent<<<NK, 256>>>(cent);
    dim3 tg(NP / 64, NC / 64);
    convert_x<<<tg, 256>>>(x);
    hmma_top2<<<NP / 128 * 4, 256, SMEM_TOTAL>>>();
    finalize<<<NP / 256, 256>>>((float*)d_out);
    rescue<<<512, 256>>>(x, (float*)d_out);
    (void)out_size;
}

// round 13
// speedup vs baseline: 1.5518x; 1.0181x over previous
#include <cuda_runtime.h>
#include <cuda_fp16.h>
#include <cstdint>

#define NB  16
#define NC  512
#define NK  512
#define NHW 4096
#define NP  (NB * NHW)   // 65536 pixels

#define RESCUE_T 0.2f

// --------------------------------------------------------------------------
// Allocation-free scratch
// --------------------------------------------------------------------------
__device__ __half g_x16[(size_t)NP * NC];   // x fp16, [p][c] K-major
__device__ __half g_c16[NK * NC];           // centers fp16 [k][c]
__device__ float  g_centT[NC * NK];         // centers fp32 transposed [c][k]
__device__ float  g_csq[NK];
__device__ unsigned long long g_partk[(size_t)NP * 4];
__device__ float              g_partv[(size_t)NP * 4];
__device__ int g_count;
__device__ int g_queue[NP];

// --------------------------------------------------------------------------
// Helpers
// --------------------------------------------------------------------------
__device__ __forceinline__ uint32_t smem_u32(const void* p) {
    uint32_t a;
    asm("{ .reg .u64 t; cvta.to.shared.u64 t, %1; cvt.u32.u64 %0, t; }"
        : "=r"(a) : "l"(p));
    return a;
}
__device__ __forceinline__ unsigned long long enc_key(float v, int k) {
    unsigned u = __float_as_uint(v);
    u = (u & 0x80000000u) ? ~u : (u | 0x80000000u);
    return ((unsigned long long)u << 32) | (unsigned)k;
}
__device__ __forceinline__ float key_val(unsigned long long key) {
    unsigned u = (unsigned)(key >> 32);
    unsigned b = (u & 0x80000000u) ? (u & 0x7FFFFFFFu) : ~u;
    return __uint_as_float(b);
}
__device__ __forceinline__ void t2merge(unsigned long long& k1, float& v2,
                                        unsigned long long ok1, float ov2) {
    if (ok1 < k1) { v2 = fminf(key_val(k1), ov2); k1 = ok1; }
    else          { v2 = fminf(v2, key_val(ok1)); }
}
__device__ __forceinline__ void ldmx4(uint32_t* r, uint32_t addr) {
    asm volatile("ldmatrix.sync.aligned.m8n8.x4.shared.b16 {%0,%1,%2,%3}, [%4];"
                 : "=r"(r[0]), "=r"(r[1]), "=r"(r[2]), "=r"(r[3]) : "r"(addr));
}
__device__ __forceinline__ void mma16816(float* d, const uint32_t* a,
                                         uint32_t b0, uint32_t b1) {
    asm volatile(
        "mma.sync.aligned.m16n8k16.row.col.f32.f16.f16.f32 "
        "{%0,%1,%2,%3}, {%4,%5,%6,%7}, {%8,%9}, {%0,%1,%2,%3};"
        : "+f"(d[0]), "+f"(d[1]), "+f"(d[2]), "+f"(d[3])
        : "r"(a[0]), "r"(a[1]), "r"(a[2]), "r"(a[3]), "r"(b0), "r"(b1));
}

// --------------------------------------------------------------------------
// Prep: one block per code k — fp16 convert + fp32 transpose + fp64 csq
// --------------------------------------------------------------------------
__global__ void conv_cent(const float* __restrict__ cent) {
    __shared__ double red[8];
    const int k = blockIdx.x;
    const int t = threadIdx.x;
    if (k == 0 && t == 0) g_count = 0;

    float f0 = cent[k * NC + t];
    float f1 = cent[k * NC + t + 256];
    g_c16[k * NC + t]        = __float2half_rn(f0);
    g_c16[k * NC + t + 256]  = __float2half_rn(f1);
    g_centT[t * NK + k]          = f0;
    g_centT[(t + 256) * NK + k]  = f1;

    double s = (double)f0 * f0 + (double)f1 * f1;
    #pragma unroll
    for (int d = 16; d > 0; d >>= 1)
        s += __shfl_xor_sync(0xFFFFFFFFu, s, d);
    if ((t & 31) == 0) red[t >> 5] = s;
    __syncthreads();
    if (t == 0) {
        double tot = 0.0;
        #pragma unroll
        for (int w = 0; w < 8; ++w) tot += red[w];
        g_csq[k] = (float)tot;
    }
}

// x (B,C,H,W) fp32 -> [p][c] fp16 via smem transpose; coalesced writes
__global__ void convert_x(const float* __restrict__ x) {
    __shared__ float s[64][65];
    const int p0 = blockIdx.x * 64;
    const int c0 = blockIdx.y * 64;
    const int b   = p0 >> 12;
    const int hw0 = p0 & 4095;
    const int t = threadIdx.x;
    const float* src = x + (size_t)b * NC * NHW + hw0;

    #pragma unroll
    for (int i = 0; i < 4; ++i) {
        int cl = i * 16 + (t >> 4);
        int pl = (t & 15) * 4;
        float4 v = *reinterpret_cast<const float4*>(src + (size_t)(c0 + cl) * NHW + pl);
        s[cl][pl] = v.x; s[cl][pl + 1] = v.y; s[cl][pl + 2] = v.z; s[cl][pl + 3] = v.w;
    }
    __syncthreads();

    {
        const int pl  = t >> 2;
        const int c16 = (t & 3) << 4;
        unsigned u[8];
        #pragma unroll
        for (int j = 0; j < 8; ++j) {
            __half2 h = __halves2half2(__float2half_rn(s[c16 + j * 2][pl]),
                                       __float2half_rn(s[c16 + j * 2 + 1][pl]));
            u[j] = *reinterpret_cast<unsigned*>(&h);
        }
        __half* dst = &g_x16[(size_t)(p0 + pl) * NC + c0 + c16];
        *reinterpret_cast<uint4*>(dst)     = make_uint4(u[0], u[1], u[2], u[3]);
        *reinterpret_cast<uint4*>(dst + 8) = make_uint4(u[4], u[5], u[6], u[7]);
    }
}

// --------------------------------------------------------------------------
// Smem: 3 stages x 32 KB (A 16 KB + B 16 KB), 128 B rows, XOR swizzle on
// 16 B units (j ^= row&7). csq after stages; top-2 scratch overlays stage 0.
// --------------------------------------------------------------------------
#define STG_BYTES 32768
#define B_OFF     16384
#define OFF_CSQ   98304
#define SMEM_TOTAL 98816

// --------------------------------------------------------------------------
// Main GEMM: CTA = 128 px x 128 codes (grid 2048). 8 stages of 64 channels,
// 3-stage cp.async ring, 1 barrier per stage, 4 k-steps per barrier window.
// Register-light loader: 2 base pointers + compile-time strides.
// --------------------------------------------------------------------------
__global__ __launch_bounds__(256, 2)
void hmma_top2() {
    extern __shared__ __align__(1024) char smem[];
    const uint32_t sb = smem_u32(smem);
    const int tid  = threadIdx.x;
    const int lane = tid & 31;
    const int wid  = tid >> 5;
    const int wm   = wid >> 2;
    const int wn   = wid & 3;

    const int grp = blockIdx.x >> 2;
    const int kc  = blockIdx.x & 3;
    const int p0  = grp * 128;

    float* cs = (float*)(smem + OFF_CSQ);
    if (tid < 128) cs[tid] = g_csq[kc * 128 + tid];

    // ---- loader bases: row0 = tid>>3 (0..31), j = tid&7 ----
    const int row0 = tid >> 3;
    const int j8   = tid & 7;
    const char* srcA = (const char*)(g_x16 + (size_t)(p0 + row0) * NC + j8 * 8);
    const char* srcB = (const char*)(g_c16 + (size_t)(kc * 128 + row0) * NC + j8 * 8);
    const uint32_t dstA = sb + row0 * 128 + ((j8 ^ (row0 & 7)) << 4);
    const uint32_t dstB = dstA + B_OFF;
    // u-th chunk: row0 + 32u  ->  src += u*32*NC*2, dst += u*4096 (row&7 const)

    // ---- ldmatrix bases (row step 16 keeps row&7 constant) ----
    const int rA  = wm * 64 + (lane & 15);
    const int swA = rA & 7;
    const int rB  = wn * 32 + (lane & 15);
    const int swB = rB & 7;
    const int khalf = lane >> 4;
    uint32_t aBase[4], bBase[2], xorA[4], xorB[4];
    #pragma unroll
    for (int mt = 0; mt < 4; ++mt) aBase[mt] = sb + (rA + mt * 16) * 128;
    #pragma unroll
    for (int nt = 0; nt < 2; ++nt) bBase[nt] = sb + B_OFF + (rB + nt * 16) * 128;
    #pragma unroll
    for (int ks = 0; ks < 4; ++ks) {
        const int jj = ks * 2 + khalf;
        xorA[ks] = (uint32_t)((jj ^ swA) << 4);
        xorB[ks] = (uint32_t)((jj ^ swB) << 4);
    }

    float acc[4][4][4];
    #pragma unroll
    for (int m = 0; m < 4; ++m)
        #pragma unroll
        for (int n = 0; n < 4; ++n)
            #pragma unroll
            for (int r = 0; r < 4; ++r) acc[m][n][r] = 0.0f;

    // ---- prologue: stages 0,1 ----
    #pragma unroll
    for (int i = 0; i < 2; ++i) {
        #pragma unroll
        for (int u = 0; u < 4; ++u) {
            asm volatile("cp.async.cg.shared.global [%0], [%1], 16;"
                :: "r"(dstA + u * 4096 + i * STG_BYTES),
                   "l"(srcA + (size_t)u * 32 * NC * 2 + i * 128) : "memory");
            asm volatile("cp.async.cg.shared.global [%0], [%1], 16;"
                :: "r"(dstB + u * 4096 + i * STG_BYTES),
                   "l"(srcB + (size_t)u * 32 * NC * 2 + i * 128) : "memory");
        }
        asm volatile("cp.async.commit_group;" ::: "memory");
    }

    #pragma unroll
    for (int i = 0; i < 8; ++i) {
        if (i < 7) asm volatile("cp.async.wait_group 1;" ::: "memory");
        else       asm volatile("cp.async.wait_group 0;" ::: "memory");
        __syncthreads();               // stage i ready; compute i-1 done
        if (i + 2 < 8) {
            const uint32_t SD = ((i + 2) % 3) * STG_BYTES;
            #pragma unroll
            for (int u = 0; u < 4; ++u) {
                asm volatile("cp.async.cg.shared.global [%0], [%1], 16;"
                    :: "r"(dstA + u * 4096 + SD),
                       "l"(srcA + (size_t)u * 32 * NC * 2 + (i + 2) * 128) : "memory");
                asm volatile("cp.async.cg.shared.global [%0], [%1], 16;"
                    :: "r"(dstB + u * 4096 + SD),
                       "l"(srcB + (size_t)u * 32 * NC * 2 + (i + 2) * 128) : "memory");
            }
            asm volatile("cp.async.commit_group;" ::: "memory");
        }
        const uint32_t S = (i % 3) * STG_BYTES;
        #pragma unroll
        for (int ks = 0; ks < 4; ++ks) {
            uint32_t ah[4][4];
            #pragma unroll
            for (int mt = 0; mt < 4; ++mt)
                ldmx4(ah[mt], aBase[mt] + S + xorA[ks]);
            #pragma unroll
            for (int nt = 0; nt < 2; ++nt) {
                uint32_t bf[4];
                ldmx4(bf, bBase[nt] + S + xorB[ks]);
                #pragma unroll
                for (int sub = 0; sub < 2; ++sub) {
                    const int nn = nt * 2 + sub;
                    #pragma unroll
                    for (int mt = 0; mt < 4; ++mt)
                        mma16816(acc[mt][nn], ah[mt], bf[sub], bf[sub + 2]);
                }
            }
        }
    }
    __syncthreads();   // before top-2 scratch overlays stage 0

    // ---- epilogue: per-row top-2 in registers, merge via shfl + smem ----
    unsigned long long* smk = (unsigned long long*)smem;     // 4 KB (stage 0)
    float*              smv = (float*)(smem + 4096);         // 2 KB
    const int r4 = lane >> 2, c2 = (lane & 3) << 1;

    #pragma unroll
    for (int mt = 0; mt < 4; ++mt) {
        unsigned long long k1a = ~0ULL, k1b = ~0ULL;
        float v2a = 3.0e38f, v2b = 3.0e38f;
        const int row = wm * 64 + mt * 16 + r4;
        #pragma unroll
        for (int nn = 0; nn < 4; ++nn) {
            #pragma unroll
            for (int cc = 0; cc < 2; ++cc) {
                const int col = wn * 32 + nn * 8 + c2 + cc;
                const int kg  = kc * 128 + col;
                float va = fmaf(-2.0f, acc[mt][nn][cc], cs[col]);
                float vb = fmaf(-2.0f, acc[mt][nn][cc + 2], cs[col]);
                unsigned long long ea = enc_key(va, kg);
                unsigned long long eb = enc_key(vb, kg);
                if (ea < k1a) { v2a = fminf(v2a, key_val(k1a)); k1a = ea; }
                else           v2a = fminf(v2a, va);
                if (eb < k1b) { v2b = fminf(v2b, key_val(k1b)); k1b = eb; }
                else           v2b = fminf(v2b, vb);
            }
        }
        #pragma unroll
        for (int d = 1; d <= 2; d <<= 1) {
            unsigned long long oka = __shfl_xor_sync(0xFFFFFFFFu, k1a, d);
            float ova              = __shfl_xor_sync(0xFFFFFFFFu, v2a, d);
            t2merge(k1a, v2a, oka, ova);
            unsigned long long okb = __shfl_xor_sync(0xFFFFFFFFu, k1b, d);
            float ovb              = __shfl_xor_sync(0xFFFFFFFFu, v2b, d);
            t2merge(k1b, v2b, okb, ovb);
        }
        if ((lane & 3) == 0) {
            smk[row * 4 + wn] = k1a;  smv[row * 4 + wn] = v2a;
            smk[(row + 8) * 4 + wn] = k1b;  smv[(row + 8) * 4 + wn] = v2b;
        }
    }
    __syncthreads();

    if (tid < 128) {
        unsigned long long k1 = smk[tid * 4];
        float v2 = smv[tid * 4];
        #pragma unroll
        for (int w = 1; w < 4; ++w) t2merge(k1, v2, smk[tid * 4 + w], smv[tid * 4 + w]);
        g_partk[(size_t)(p0 + tid) * 4 + kc] = k1;
        g_partv[(size_t)(p0 + tid) * 4 + kc] = v2;
    }
}

// --------------------------------------------------------------------------
// Finalize: global top-2 across chunks; enqueue tight margins for rescue.
// --------------------------------------------------------------------------
__global__ void finalize(float* __restrict__ out) {
    int p = blockIdx.x * 256 + threadIdx.x;
    unsigned long long k1 = g_partk[(size_t)p * 4];
    float v2 = g_partv[(size_t)p * 4];
    #pragma unroll
    for (int c = 1; c < 4; ++c)
        t2merge(k1, v2, g_partk[(size_t)p * 4 + c], g_partv[(size_t)p * 4 + c]);
    out[p] = (float)(int)(unsigned)(k1 & 0xFFFFFFFFULL);
    if (v2 - key_val(k1) < RESCUE_T) {
        int s = atomicAdd(&g_count, 1);
        g_queue[s] = p;
    }
}

// --------------------------------------------------------------------------
// Rescue: exact fp32 re-evaluation; 8 px/block batches, unrolled gather.
// --------------------------------------------------------------------------
__global__ __launch_bounds__(256, 2)
void rescue(const float* __restrict__ x, float* __restrict__ out) {
    __shared__ float xs[8][512];
    __shared__ unsigned long long best[8];
    const int t = threadIdx.x;
    const int cnt = g_count;

    for (int base = blockIdx.x * 8; base < cnt; base += 512 * 8) {
        const int nv = min(8, cnt - base);
        if (t < 8) best[t] = ~0ULL;
        #pragma unroll
        for (int i = 0; i < 8; ++i) {
            if (i < nv) {
                int p = g_queue[base + i];
                int b = p >> 12, hw = p & 4095;
                const float* src = x + (size_t)b * NC * NHW + hw;
                xs[i][t]       = src[(size_t)t * NHW];
                xs[i][t + 256] = src[(size_t)(t + 256) * NHW];
            }
        }
        __syncthreads();

        float a0[8], a1[8];
        #pragma unroll
        for (int i = 0; i < 8; ++i) { a0[i] = 0.0f; a1[i] = 0.0f; }
        const float cq0 = g_csq[t], cq1 = g_csq[t + 256];

        #pragma unroll 4
        for (int cc = 0; cc < 512; ++cc) {
            float c0v = g_centT[cc * NK + t];
            float c1v = g_centT[cc * NK + t + 256];
            #pragma unroll
            for (int i = 0; i < 8; ++i) {
                float xv = xs[i][cc];
                a0[i] = fmaf(xv, c0v, a0[i]);
                a1[i] = fmaf(xv, c1v, a1[i]);
            }
        }
        #pragma unroll
        for (int i = 0; i < 8; ++i) {
            if (i < nv) {
                unsigned long long e0 = enc_key(fmaf(-2.0f, a0[i], cq0), t);
                unsigned long long e1 = enc_key(fmaf(-2.0f, a1[i], cq1), t + 256);
                atomicMin(&best[i], e0 < e1 ? e0 : e1);
            }
        }
        __syncthreads();
        if (t < nv)
            out[g_queue[base + t]] =
                (float)(int)(unsigned)(best[t] & 0xFFFFFFFFULL);
        __syncthreads();
    }
}

// --------------------------------------------------------------------------
// Launch
// --------------------------------------------------------------------------
extern "C" void kernel_launch(void* const* d_in, const int* in_sizes, int n_in,
                              void* d_out, int out_size) {
    const float* x    = (const float*)d_in[0];
    const float* cent = (const float*)d_in[1];
    if (n_in >= 2 && in_sizes[0] < in_sizes[1]) {
        const float* t = x; x = cent; cent = t;
    }

    cudaFuncSetAttribute(hmma_top2,
                         cudaFuncAttributeMaxDynamicSharedMemorySize, SMEM_TOTAL);

    conv_cent<<<NK, 256>>>(cent);
    dim3 tg(NP / 64, NC / 64);
    convert_x<<<tg, 256>>>(x);
    hmma_top2<<<NP / 128 * 4, 256, SMEM_TOTAL>>>();
    finalize<<<NP / 256, 256>>>((float*)d_out);
    rescue<<<512, 256>>>(x, (float*)d_out);
    (void)out_size;
}